// round 16
// baseline (speedup 1.0000x reference)
#include <cuda_runtime.h>
#include <cuda_fp16.h>
#include <cstdint>

// ============================================================================
// RNN_BN_simple, round 16: r14 base + weight-prep absorbed into idle windows.
//  - r15's pure-GEMM g1 REVERTED (2 CTAs/SM did not help: g1 is L1-bound).
//  - prep_all launch eliminated:
//      * W1 conversion folded into stats_kernel (4 quads/thread, exact).
//      * W2+W3 conversion folded into g1's prologue latency window
//        (fire-and-forget streaming under the chunk-0 cp.async wait).
//  - fp16 h1+h2, single-product fp16 HMMA, BN=256/BK=64, staged epilogue.
// ============================================================================

namespace {
constexpr int BB = 4096, TT = 64, PP = 64, HH = 512;
constexpr float BN_EPS = 1e-3f;
constexpr int SPLITS0 = 32;
constexpr int MBLK = BB / 128;
}

// ---------------- scratch ----------------------------------------------------
__device__ __align__(16) __half g_h1[(size_t)TT * BB * HH];
__device__ __align__(16) __half g_h2[(size_t)TT * BB * HH];
__device__ float g_psum[MBLK * TT * HH];
__device__ float g_psq [MBLK * TT * HH];
__device__ float g_s[TT * HH];
__device__ float g_c[TT * HH];
__device__ __align__(16) __half g_w1[(size_t)TT * PP * HH];
__device__ __align__(16) __half g_w2[(size_t)TT * HH * HH];
__device__ __align__(16) __half g_w3[(size_t)TT * HH * PP];

// ---------------- helpers ------------------------------------------------------
__device__ __forceinline__ uint32_t smem_u32(const void* p) {
    uint32_t a;
    asm("{ .reg .u64 t; cvta.to.shared.u64 t, %1; cvt.u32.u64 %0, t; }"
        : "=r"(a) : "l"(p));
    return a;
}
__device__ __forceinline__ void ldm_x4(uint32_t* r, uint32_t addr) {
    asm volatile("ldmatrix.sync.aligned.m8n8.x4.shared.b16 {%0,%1,%2,%3}, [%4];"
                 : "=r"(r[0]), "=r"(r[1]), "=r"(r[2]), "=r"(r[3]) : "r"(addr));
}
__device__ __forceinline__ void ldm_x4t(uint32_t* r, uint32_t addr) {
    asm volatile("ldmatrix.sync.aligned.m8n8.x4.trans.shared.b16 {%0,%1,%2,%3}, [%4];"
                 : "=r"(r[0]), "=r"(r[1]), "=r"(r[2]), "=r"(r[3]) : "r"(addr));
}
__device__ __forceinline__ void mma_f16(float* c, const uint32_t* a,
                                        const uint32_t* b) {
    asm volatile(
        "mma.sync.aligned.m16n8k16.row.col.f32.f16.f16.f32 "
        "{%0,%1,%2,%3}, {%4,%5,%6,%7}, {%8,%9}, {%0,%1,%2,%3};"
        : "+f"(c[0]), "+f"(c[1]), "+f"(c[2]), "+f"(c[3])
        : "r"(a[0]), "r"(a[1]), "r"(a[2]), "r"(a[3]), "r"(b[0]), "r"(b[1]));
}
__device__ __forceinline__ void cp16(uint32_t dst, const void* src) {
    asm volatile("cp.async.cg.shared.global [%0], [%1], 16;"
                 :: "r"(dst), "l"(src));
}
__device__ __forceinline__ uint2 pack4h(float y0, float y1, float y2, float y3) {
    __half2 h01 = __floats2half2_rn(y0, y1);
    __half2 h23 = __floats2half2_rn(y2, y3);
    return make_uint2(*reinterpret_cast<uint32_t*>(&h01),
                      *reinterpret_cast<uint32_t*>(&h23));
}
template <typename T> struct avec;
template <> struct avec<float>  { using type = float4; };
template <> struct avec<__half> { using type = uint2;  };
__device__ __forceinline__ void unpack4(const float4& v, float& a, float& b,
                                        float& c, float& d) {
    a = v.x; b = v.y; c = v.z; d = v.w;
}
__device__ __forceinline__ void unpack4(const uint2& v, float& a, float& b,
                                        float& c, float& d) {
    __half2 p01 = *reinterpret_cast<const __half2*>(&v.x);
    __half2 p23 = *reinterpret_cast<const __half2*>(&v.y);
    float2 f01 = __half22float2(p01);
    float2 f23 = __half22float2(p23);
    a = f01.x; b = f01.y; c = f23.x; d = f23.y;
}
__device__ __forceinline__ void store2(float* p, float a, float b) {
    *(float2*)p = make_float2(a, b);
}
__device__ __forceinline__ void store2(__half* p, float a, float b) {
    *(__half2*)p = __floats2half2_rn(a, b);
}

// ---------------- BN stats for prices (+ W1 fp16 conversion) --------------------
__global__ void stats_kernel(const float* __restrict__ x, size_t t_stride,
                             int row_stride, int D, int rows_per_split,
                             const float* __restrict__ W1c) {
    // absorbed W1 prep: 131072 threads x 4 quads = exactly TT*PP*HH/4 quads
    {
        size_t fid = ((size_t)(blockIdx.x * gridDim.y + blockIdx.y)) * blockDim.x +
                     threadIdx.x;
        #pragma unroll
        for (int q = 0; q < 4; q++) {
            size_t j = fid * 4 + q;
            float4 w = ((const float4*)W1c)[j];
            ((uint2*)g_w1)[j] = pack4h(w.x, w.y, w.z, w.w);
        }
    }
    const int t = blockIdx.x, split = blockIdx.y;
    const float* xt = x + (size_t)t * t_stride +
                      (size_t)split * rows_per_split * row_stride;
    for (int d = threadIdx.x; d < D; d += blockDim.x) {
        float s0 = 0.f, s1 = 0.f, q0 = 0.f, q1 = 0.f;
        #pragma unroll 2
        for (int r = 0; r < rows_per_split; r += 2) {
            float v0 = xt[(size_t)r * row_stride + d];
            float v1 = xt[(size_t)(r + 1) * row_stride + d];
            s0 += v0; q0 = fmaf(v0, v0, q0);
            s1 += v1; q1 = fmaf(v1, v1, q1);
        }
        int n = gridDim.x * D, i = t * D + d;
        g_psum[split * n + i] = s0 + s1;
        g_psq [split * n + i] = q0 + q1;
    }
}
__global__ void finalize_kernel(const float* __restrict__ gamma,
                                const float* __restrict__ beta, int n,
                                float invB, int nparts) {
    int i = blockIdx.x * blockDim.x + threadIdx.x;
    if (i >= n) return;
    float s = 0.f, q = 0.f;
    for (int sp = 0; sp < nparts; sp++) {
        s += g_psum[(size_t)sp * n + i];
        q += g_psq [(size_t)sp * n + i];
    }
    float m = s * invB;
    float v = fmaxf(fmaf(-m, m, q * invB), 0.f);
    float sc = gamma[i] * rsqrtf(v + BN_EPS);
    g_s[i] = sc;
    g_c[i] = fmaf(-m, sc, beta[i]);
}

// ---------------- single-product fp16 HMMA GEMM -----------------------------------
// out[t,m,n] = sum_k prelu(A[t,m,k]*s+c) * W[t,k,n] + bias[t,n]
// Epilogue: acc -> padded SMEM tile -> coalesced uint4 stores.
// If PREP: each CTA converts 5 strided quads of W2/W3 fp32->fp16 in the
// prologue latency window (fire-and-forget; consumers launch later).
template <int BN, int BK, int KTOT, int NTOT, bool RELU, bool STATS, bool PREP,
          typename AT, typename OT>
__global__ void __launch_bounds__(256)
gemm_mma(const AT* __restrict__ A, size_t a_t, int a_rs,
         const __half* __restrict__ W,
         const float* __restrict__ bias,
         OT* __restrict__ out, size_t o_t, int o_rs,
         const float* __restrict__ prep2, const float* __restrict__ prep3) {
    using AVec = typename avec<AT>::type;
    constexpr int BM = 128;
    constexpr int AROW = BK + 8, WROW = BN + 8;
    constexpr int A_BYTES = BM * AROW * 2, W_BYTES = BK * WROW * 2;
    constexpr int WHO = A_BYTES;
    constexpr int STAGE = A_BYTES + W_BYTES;
    constexpr int KT = KTOT / BK;
    constexpr int WARPS_N = 4;
    constexpr int WTM = BM / 2, WTN = BN / WARPS_N;
    constexpr int MT = WTM / 16, NT = WTN / 8;
    constexpr int SEGS = BN / 8;
    constexpr int AV = BM * BK / (4 * 256);
    constexpr int KQL = BK / 4;
    constexpr int RPV = 256 / KQL;
    constexpr int NK16 = BK / 16;
    constexpr int OROW = BN + 16 / (int)sizeof(OT);
    constexpr int OROW_B = OROW * (int)sizeof(OT);
    constexpr int SBUF_OFF = BM * OROW_B;

    extern __shared__ char smem[];
    const uint32_t sb = smem_u32(smem);
    const int tid = threadIdx.x, wid = tid >> 5, lane = tid & 31;
    const int wm = wid / WARPS_N, wn = wid % WARPS_N;
    const int t = blockIdx.z, n0 = blockIdx.x * BN, m0 = blockIdx.y * BM;

    const int kq = tid % KQL, rowb = tid / KQL;
    const AT* At = A + (size_t)t * a_t + (size_t)m0 * a_rs;
    const float* sArr = g_s + t * KTOT;
    const float* cArr = g_c + t * KTOT;
    const __half* WT = W + (size_t)t * KTOT * NTOT + n0;

    AVec areg[AV];
    float4 sv, cv;
    auto ldgA = [&](int kt) {
        const AT* base = At + kt * BK + kq * 4;
        #pragma unroll
        for (int v = 0; v < AV; v++)
            areg[v] = *(const AVec*)(base + (size_t)(rowb + v * RPV) * a_rs);
        sv = *(const float4*)(sArr + kt * BK + kq * 4);
        cv = *(const float4*)(cArr + kt * BK + kq * 4);
    };
    auto stsA = [&](int st) {
        char* hb = smem + st * STAGE;
        #pragma unroll
        for (int v = 0; v < AV; v++) {
            float x0, x1, x2, x3;
            unpack4(areg[v], x0, x1, x2, x3);
            float y0 = fmaf(x0, sv.x, cv.x);
            float y1 = fmaf(x1, sv.y, cv.y);
            float y2 = fmaf(x2, sv.z, cv.z);
            float y3 = fmaf(x3, sv.w, cv.w);
            if (RELU) {
                y0 = fmaxf(y0, 0.f); y1 = fmaxf(y1, 0.f);
                y2 = fmaxf(y2, 0.f); y3 = fmaxf(y3, 0.f);
            }
            uint32_t off = (uint32_t)((rowb + v * RPV) * AROW + kq * 4) * 2;
            *(uint2*)(hb + off) = pack4h(y0, y1, y2, y3);
        }
    };
    auto cpW = [&](int kt, int st) {
        const uint32_t stb = sb + st * STAGE;
        #pragma unroll
        for (int i = tid; i < BK * SEGS; i += 256) {
            int row = i / SEGS, seg = i % SEGS;
            size_t g = (size_t)(kt * BK + row) * NTOT + seg * 8;
            cp16(stb + WHO + row * (WROW * 2) + seg * 16, WT + g);
        }
        asm volatile("cp.async.commit_group;" ::: "memory");
    };

    float acc[MT][NT][4];
    #pragma unroll
    for (int i = 0; i < MT; i++)
        #pragma unroll
        for (int j = 0; j < NT; j++)
            #pragma unroll
            for (int k = 0; k < 4; k++) acc[i][j][k] = 0.f;

    const int lrow = lane & 15, lsel = lane >> 4;

    auto compute_k16 = [&](uint32_t stb, int k16) {
        uint32_t ah[MT][4];
        #pragma unroll
        for (int mt = 0; mt < MT; mt++) {
            uint32_t off = (uint32_t)((wm * WTM + mt * 16 + lrow) * AROW +
                                      k16 * 16 + lsel * 8) * 2;
            ldm_x4(ah[mt], stb + off);
        }
        uint32_t bq[NT][2];
        #pragma unroll
        for (int np = 0; np < NT / 2; np++) {
            uint32_t off = (uint32_t)((k16 * 16 + lrow) * WROW + wn * WTN +
                                      np * 16 + lsel * 8) * 2;
            uint32_t r[4];
            ldm_x4t(r, stb + WHO + off);
            bq[2*np][0] = r[0]; bq[2*np][1] = r[1];
            bq[2*np+1][0] = r[2]; bq[2*np+1][1] = r[3];
        }
        #pragma unroll
        for (int mt = 0; mt < MT; mt++)
            #pragma unroll
            for (int nt = 0; nt < NT; nt++) mma_f16(acc[mt][nt], ah[mt], bq[nt]);
    };

    // prologue
    ldgA(0);
    cpW(0, 0);
    stsA(0);

    // absorbed W2/W3 prep: streaming under the chunk-0 wait window
    if (PREP) {
        constexpr size_t Q2 = (size_t)TT * HH * HH / 4;
        constexpr size_t Q3 = (size_t)TT * HH * PP / 4;
        size_t fid = ((size_t)((blockIdx.z * gridDim.y + blockIdx.y) * gridDim.x +
                               blockIdx.x)) * 256 + tid;
        size_t tot = (size_t)gridDim.x * gridDim.y * gridDim.z * 256;
        #pragma unroll
        for (int q = 0; q < 5; q++) {
            size_t j = fid + (size_t)q * tot;
            if (j < Q2) {
                float4 w = ((const float4*)prep2)[j];
                ((uint2*)g_w2)[j] = pack4h(w.x, w.y, w.z, w.w);
            } else if (j < Q2 + Q3) {
                size_t k2 = j - Q2;
                float4 w = ((const float4*)prep3)[k2];
                ((uint2*)g_w3)[k2] = pack4h(w.x, w.y, w.z, w.w);
            }
        }
    }

    #pragma unroll 1
    for (int kt = 0; kt < KT; kt++) {
        const int st = kt & 1;
        asm volatile("cp.async.wait_group 0;" ::: "memory");
        __syncthreads();
        const bool more = (kt + 1 < KT);
        if (more) { cpW(kt + 1, st ^ 1); ldgA(kt + 1); }
        const uint32_t stb = sb + st * STAGE;
        compute_k16(stb, 0);
        if (more) stsA(st ^ 1);      // overlapped: writes the other stage
        #pragma unroll
        for (int k16 = 1; k16 < NK16; k16++) compute_k16(stb, k16);
    }
    __syncthreads();   // stage smem dead; reused for output staging + stats

    // ---- epilogue: bias -> SMEM stage (+stats from regs), then coalesced STG ----
    const int r0 = lane >> 2, c0 = (lane & 3) * 2;
    #pragma unroll
    for (int nt = 0; nt < NT; nt++) {
        float2 bv = *(const float2*)(bias + t * NTOT + n0 + wn * WTN + nt * 8 + c0);
        #pragma unroll
        for (int mt = 0; mt < MT; mt++) {
            acc[mt][nt][0] += bv.x; acc[mt][nt][1] += bv.y;
            acc[mt][nt][2] += bv.x; acc[mt][nt][3] += bv.y;
        }
    }
    #pragma unroll
    for (int mt = 0; mt < MT; mt++) {
        #pragma unroll
        for (int nt = 0; nt < NT; nt++) {
            int col = wn * WTN + nt * 8 + c0;
            int row = wm * WTM + mt * 16 + r0;
            OT* p0 = (OT*)(smem + (size_t)row * OROW_B) + col;
            OT* p1 = (OT*)(smem + (size_t)(row + 8) * OROW_B) + col;
            store2(p0, acc[mt][nt][0], acc[mt][nt][1]);
            store2(p1, acc[mt][nt][2], acc[mt][nt][3]);
        }
    }
    if (STATS) {
        float* sbuf = (float*)(smem + SBUF_OFF);   // [4][BN]
        #pragma unroll
        for (int nt = 0; nt < NT; nt++) {
            #pragma unroll
            for (int j = 0; j < 2; j++) {
                float s = 0.f, q = 0.f;
                #pragma unroll
                for (int mt = 0; mt < MT; mt++) {
                    float v0 = acc[mt][nt][j], v1 = acc[mt][nt][2 + j];
                    s += v0 + v1;
                    q = fmaf(v0, v0, q); q = fmaf(v1, v1, q);
                }
                #pragma unroll
                for (int msk = 4; msk <= 16; msk <<= 1) {
                    s += __shfl_xor_sync(0xffffffffu, s, msk);
                    q += __shfl_xor_sync(0xffffffffu, q, msk);
                }
                if (r0 == 0) {
                    int col = wn * WTN + nt * 8 + c0 + j;
                    sbuf[(wm * 2 + 0) * BN + col] = s;
                    sbuf[(wm * 2 + 1) * BN + col] = q;
                }
            }
        }
    }
    __syncthreads();   // staging tile + stats scratch visible
    {
        constexpr int VPR = BN * (int)sizeof(OT) / 16;   // uint4 per row
        #pragma unroll
        for (int i = tid; i < BM * VPR; i += 256) {
            int row = i / VPR, v = i % VPR;
            uint4 val = *(const uint4*)(smem + (size_t)row * OROW_B + v * 16);
            char* dst = (char*)(out + (size_t)t * o_t +
                                (size_t)(m0 + row) * o_rs + n0) + v * 16;
            *(uint4*)dst = val;
        }
    }
    if (STATS) {
        float* sbuf = (float*)(smem + SBUF_OFF);
        for (int cix = tid; cix < BN; cix += 256) {
            float ss = sbuf[0 * BN + cix] + sbuf[2 * BN + cix];
            float qq = sbuf[1 * BN + cix] + sbuf[3 * BN + cix];
            size_t pi = (size_t)blockIdx.y * (TT * NTOT) + (size_t)t * NTOT + n0 + cix;
            g_psum[pi] = ss;
            g_psq [pi] = qq;
        }
    }
}

// ---------------- launch --------------------------------------------------------
extern "C" void kernel_launch(void* const* d_in, const int* in_sizes, int n_in,
                              void* d_out, int out_size) {
    (void)in_sizes; (void)n_in; (void)out_size;
    const float* prices = (const float*)d_in[0];
    const float* bn0_g  = (const float*)d_in[1];
    const float* bn0_b  = (const float*)d_in[2];
    const float* W1     = (const float*)d_in[3];
    const float* b1     = (const float*)d_in[4];
    const float* bn1_g  = (const float*)d_in[5];
    const float* bn1_b  = (const float*)d_in[6];
    const float* W2     = (const float*)d_in[7];
    const float* b2     = (const float*)d_in[8];
    const float* bn2_g  = (const float*)d_in[9];
    const float* bn2_b  = (const float*)d_in[10];
    const float* W3     = (const float*)d_in[11];
    const float* b3     = (const float*)d_in[12];
    float* out = (float*)d_out;

    __half *hp1, *hp2, *w1, *w2, *w3;
    cudaGetSymbolAddress((void**)&hp1, g_h1);
    cudaGetSymbolAddress((void**)&hp2, g_h2);
    cudaGetSymbolAddress((void**)&w1, g_w1);
    cudaGetSymbolAddress((void**)&w2, g_w2);
    cudaGetSymbolAddress((void**)&w3, g_w3);

    const float invB = 1.0f / (float)BB;

    auto g1 = gemm_mma<256, 64, 64,  512, false, true,  true,  float,  __half>;
    auto g2 = gemm_mma<256, 64, 512, 512, true,  true,  false, __half, __half>;
    auto g3 = gemm_mma<64,  64, 512, 64,  true,  false, false, __half, float>;
    constexpr int STAGE_256 = 128 * 72 * 2 + 64 * 264 * 2;  // 52224
    constexpr int STAGE_64  = 128 * 72 * 2 + 64 * 72 * 2;   // 27648
    constexpr int SM1 = 67584 + 4096;                        // out staging + stats
    constexpr int SM2 = (2 * STAGE_256 > 67584 + 4096) ? 2 * STAGE_256
                                                       : 67584 + 4096; // 104448
    constexpr int SM3 = 2 * STAGE_64;                        // 55296 > 34816
    cudaFuncSetAttribute(g1, cudaFuncAttributeMaxDynamicSharedMemorySize, SM1);
    cudaFuncSetAttribute(g2, cudaFuncAttributeMaxDynamicSharedMemorySize, SM2);
    cudaFuncSetAttribute(g3, cudaFuncAttributeMaxDynamicSharedMemorySize, SM3);

    // 0: BN0 stats (+ absorbed W1 fp16 conversion)
    stats_kernel<<<dim3(TT, SPLITS0), 64>>>(prices, (size_t)PP, TT * PP, PP,
                                            BB / SPLITS0, W1);
    // 1: finalize0
    finalize_kernel<<<(TT * PP + 255) / 256, 256>>>(bn0_g, bn0_b, TT * PP, invB,
                                                    SPLITS0);
    // 2: g1 (+ absorbed W2/W3 conversion in prologue window)
    g1<<<dim3(HH / 256, BB / 128, TT), 256, SM1>>>(
        prices, (size_t)PP, TT * PP, w1, b1, hp1, (size_t)BB * HH, HH, W2, W3);
    // 3: finalize1 -> g2
    finalize_kernel<<<(TT * HH + 255) / 256, 256>>>(bn1_g, bn1_b, TT * HH, invB,
                                                    MBLK);
    g2<<<dim3(HH / 256, BB / 128, TT), 256, SM2>>>(
        hp1, (size_t)BB * HH, HH, w2, b2, hp2, (size_t)BB * HH, HH,
        nullptr, nullptr);
    // 5: finalize2 -> g3
    finalize_kernel<<<(TT * HH + 255) / 256, 256>>>(bn2_g, bn2_b, TT * HH, invB,
                                                    MBLK);
    g3<<<dim3(1, BB / 128, TT), 256, SM3>>>(
        hp2, (size_t)BB * HH, HH, w3, b3, out, (size_t)PP, TT * PP,
        nullptr, nullptr);
}

// round 17
// speedup vs baseline: 1.0555x; 1.0555x over previous
#include <cuda_runtime.h>
#include <cuda_fp16.h>
#include <cstdint>

// ============================================================================
// RNN_BN_simple, round 17: r14 base + weight prep on a forked capture stream.
//  - r16's in-GEMM prep absorption REVERTED (L1 contention inside g1, +42us).
//  - prep_w1 / prep_w23 run on a side stream, forked/joined with events
//    (standard graph-capture fork): W1 joins before g1 (hidden under stats),
//    W2/W3 join before g2 (hidden under g1). GEMMs byte-identical to r14.
//  - fp16 h1+h2, single-product fp16 HMMA, BN=256/BK=64, staged epilogue.
// ============================================================================

namespace {
constexpr int BB = 4096, TT = 64, PP = 64, HH = 512;
constexpr float BN_EPS = 1e-3f;
constexpr int SPLITS0 = 32;
constexpr int MBLK = BB / 128;
}

// ---------------- scratch ----------------------------------------------------
__device__ __align__(16) __half g_h1[(size_t)TT * BB * HH];
__device__ __align__(16) __half g_h2[(size_t)TT * BB * HH];
__device__ float g_psum[MBLK * TT * HH];
__device__ float g_psq [MBLK * TT * HH];
__device__ float g_s[TT * HH];
__device__ float g_c[TT * HH];
__device__ __align__(16) __half g_w1[(size_t)TT * PP * HH];
__device__ __align__(16) __half g_w2[(size_t)TT * HH * HH];
__device__ __align__(16) __half g_w3[(size_t)TT * HH * PP];

// ---------------- helpers ------------------------------------------------------
__device__ __forceinline__ uint32_t smem_u32(const void* p) {
    uint32_t a;
    asm("{ .reg .u64 t; cvta.to.shared.u64 t, %1; cvt.u32.u64 %0, t; }"
        : "=r"(a) : "l"(p));
    return a;
}
__device__ __forceinline__ void ldm_x4(uint32_t* r, uint32_t addr) {
    asm volatile("ldmatrix.sync.aligned.m8n8.x4.shared.b16 {%0,%1,%2,%3}, [%4];"
                 : "=r"(r[0]), "=r"(r[1]), "=r"(r[2]), "=r"(r[3]) : "r"(addr));
}
__device__ __forceinline__ void ldm_x4t(uint32_t* r, uint32_t addr) {
    asm volatile("ldmatrix.sync.aligned.m8n8.x4.trans.shared.b16 {%0,%1,%2,%3}, [%4];"
                 : "=r"(r[0]), "=r"(r[1]), "=r"(r[2]), "=r"(r[3]) : "r"(addr));
}
__device__ __forceinline__ void mma_f16(float* c, const uint32_t* a,
                                        const uint32_t* b) {
    asm volatile(
        "mma.sync.aligned.m16n8k16.row.col.f32.f16.f16.f32 "
        "{%0,%1,%2,%3}, {%4,%5,%6,%7}, {%8,%9}, {%0,%1,%2,%3};"
        : "+f"(c[0]), "+f"(c[1]), "+f"(c[2]), "+f"(c[3])
        : "r"(a[0]), "r"(a[1]), "r"(a[2]), "r"(a[3]), "r"(b[0]), "r"(b[1]));
}
__device__ __forceinline__ void cp16(uint32_t dst, const void* src) {
    asm volatile("cp.async.cg.shared.global [%0], [%1], 16;"
                 :: "r"(dst), "l"(src));
}
__device__ __forceinline__ uint2 pack4h(float y0, float y1, float y2, float y3) {
    __half2 h01 = __floats2half2_rn(y0, y1);
    __half2 h23 = __floats2half2_rn(y2, y3);
    return make_uint2(*reinterpret_cast<uint32_t*>(&h01),
                      *reinterpret_cast<uint32_t*>(&h23));
}
template <typename T> struct avec;
template <> struct avec<float>  { using type = float4; };
template <> struct avec<__half> { using type = uint2;  };
__device__ __forceinline__ void unpack4(const float4& v, float& a, float& b,
                                        float& c, float& d) {
    a = v.x; b = v.y; c = v.z; d = v.w;
}
__device__ __forceinline__ void unpack4(const uint2& v, float& a, float& b,
                                        float& c, float& d) {
    __half2 p01 = *reinterpret_cast<const __half2*>(&v.x);
    __half2 p23 = *reinterpret_cast<const __half2*>(&v.y);
    float2 f01 = __half22float2(p01);
    float2 f23 = __half22float2(p23);
    a = f01.x; b = f01.y; c = f23.x; d = f23.y;
}
__device__ __forceinline__ void store2(float* p, float a, float b) {
    *(float2*)p = make_float2(a, b);
}
__device__ __forceinline__ void store2(__half* p, float a, float b) {
    *(__half2*)p = __floats2half2_rn(a, b);
}

// ---------------- BN stats for prices ------------------------------------------
__global__ void stats_kernel(const float* __restrict__ x, size_t t_stride,
                             int row_stride, int D, int rows_per_split) {
    const int t = blockIdx.x, split = blockIdx.y;
    const float* xt = x + (size_t)t * t_stride +
                      (size_t)split * rows_per_split * row_stride;
    for (int d = threadIdx.x; d < D; d += blockDim.x) {
        float s0 = 0.f, s1 = 0.f, q0 = 0.f, q1 = 0.f;
        #pragma unroll 2
        for (int r = 0; r < rows_per_split; r += 2) {
            float v0 = xt[(size_t)r * row_stride + d];
            float v1 = xt[(size_t)(r + 1) * row_stride + d];
            s0 += v0; q0 = fmaf(v0, v0, q0);
            s1 += v1; q1 = fmaf(v1, v1, q1);
        }
        int n = gridDim.x * D, i = t * D + d;
        g_psum[split * n + i] = s0 + s1;
        g_psq [split * n + i] = q0 + q1;
    }
}
__global__ void finalize_kernel(const float* __restrict__ gamma,
                                const float* __restrict__ beta, int n,
                                float invB, int nparts) {
    int i = blockIdx.x * blockDim.x + threadIdx.x;
    if (i >= n) return;
    float s = 0.f, q = 0.f;
    for (int sp = 0; sp < nparts; sp++) {
        s += g_psum[(size_t)sp * n + i];
        q += g_psq [(size_t)sp * n + i];
    }
    float m = s * invB;
    float v = fmaxf(fmaf(-m, m, q * invB), 0.f);
    float sc = gamma[i] * rsqrtf(v + BN_EPS);
    g_s[i] = sc;
    g_c[i] = fmaf(-m, sc, beta[i]);
}

// ---------------- weight prep (side stream) --------------------------------------
__global__ void prep_w1k(const float* __restrict__ W1) {
    constexpr size_t N1Q = (size_t)TT * PP * HH / 4;
    size_t i = (size_t)blockIdx.x * blockDim.x + threadIdx.x;
    if (i >= N1Q) return;
    float4 w = ((const float4*)W1)[i];
    ((uint2*)g_w1)[i] = pack4h(w.x, w.y, w.z, w.w);
}
__global__ void prep_w23(const float* __restrict__ W2, const float* __restrict__ W3) {
    constexpr size_t N2Q = (size_t)TT * HH * HH / 4;
    constexpr size_t N3Q = (size_t)TT * HH * PP / 4;
    size_t i = (size_t)blockIdx.x * blockDim.x + threadIdx.x;
    const float* src; __half* dst; size_t j;
    if (i < N2Q)            { src = W2; dst = g_w2; j = i; }
    else if (i < N2Q + N3Q) { src = W3; dst = g_w3; j = i - N2Q; }
    else return;
    float4 w = ((const float4*)src)[j];
    ((uint2*)dst)[j] = pack4h(w.x, w.y, w.z, w.w);
}

// ---------------- single-product fp16 HMMA GEMM (r14 verbatim) --------------------
template <int BN, int BK, int KTOT, int NTOT, bool RELU, bool STATS,
          typename AT, typename OT>
__global__ void __launch_bounds__(256)
gemm_mma(const AT* __restrict__ A, size_t a_t, int a_rs,
         const __half* __restrict__ W,
         const float* __restrict__ bias,
         OT* __restrict__ out, size_t o_t, int o_rs) {
    using AVec = typename avec<AT>::type;
    constexpr int BM = 128;
    constexpr int AROW = BK + 8, WROW = BN + 8;
    constexpr int A_BYTES = BM * AROW * 2, W_BYTES = BK * WROW * 2;
    constexpr int WHO = A_BYTES;
    constexpr int STAGE = A_BYTES + W_BYTES;
    constexpr int KT = KTOT / BK;
    constexpr int WARPS_N = 4;
    constexpr int WTM = BM / 2, WTN = BN / WARPS_N;
    constexpr int MT = WTM / 16, NT = WTN / 8;
    constexpr int SEGS = BN / 8;
    constexpr int AV = BM * BK / (4 * 256);
    constexpr int KQL = BK / 4;
    constexpr int RPV = 256 / KQL;
    constexpr int NK16 = BK / 16;
    constexpr int OROW = BN + 16 / (int)sizeof(OT);
    constexpr int OROW_B = OROW * (int)sizeof(OT);
    constexpr int SBUF_OFF = BM * OROW_B;

    extern __shared__ char smem[];
    const uint32_t sb = smem_u32(smem);
    const int tid = threadIdx.x, wid = tid >> 5, lane = tid & 31;
    const int wm = wid / WARPS_N, wn = wid % WARPS_N;
    const int t = blockIdx.z, n0 = blockIdx.x * BN, m0 = blockIdx.y * BM;

    const int kq = tid % KQL, rowb = tid / KQL;
    const AT* At = A + (size_t)t * a_t + (size_t)m0 * a_rs;
    const float* sArr = g_s + t * KTOT;
    const float* cArr = g_c + t * KTOT;
    const __half* WT = W + (size_t)t * KTOT * NTOT + n0;

    AVec areg[AV];
    float4 sv, cv;
    auto ldgA = [&](int kt) {
        const AT* base = At + kt * BK + kq * 4;
        #pragma unroll
        for (int v = 0; v < AV; v++)
            areg[v] = *(const AVec*)(base + (size_t)(rowb + v * RPV) * a_rs);
        sv = *(const float4*)(sArr + kt * BK + kq * 4);
        cv = *(const float4*)(cArr + kt * BK + kq * 4);
    };
    auto stsA = [&](int st) {
        char* hb = smem + st * STAGE;
        #pragma unroll
        for (int v = 0; v < AV; v++) {
            float x0, x1, x2, x3;
            unpack4(areg[v], x0, x1, x2, x3);
            float y0 = fmaf(x0, sv.x, cv.x);
            float y1 = fmaf(x1, sv.y, cv.y);
            float y2 = fmaf(x2, sv.z, cv.z);
            float y3 = fmaf(x3, sv.w, cv.w);
            if (RELU) {
                y0 = fmaxf(y0, 0.f); y1 = fmaxf(y1, 0.f);
                y2 = fmaxf(y2, 0.f); y3 = fmaxf(y3, 0.f);
            }
            uint32_t off = (uint32_t)((rowb + v * RPV) * AROW + kq * 4) * 2;
            *(uint2*)(hb + off) = pack4h(y0, y1, y2, y3);
        }
    };
    auto cpW = [&](int kt, int st) {
        const uint32_t stb = sb + st * STAGE;
        #pragma unroll
        for (int i = tid; i < BK * SEGS; i += 256) {
            int row = i / SEGS, seg = i % SEGS;
            size_t g = (size_t)(kt * BK + row) * NTOT + seg * 8;
            cp16(stb + WHO + row * (WROW * 2) + seg * 16, WT + g);
        }
        asm volatile("cp.async.commit_group;" ::: "memory");
    };

    float acc[MT][NT][4];
    #pragma unroll
    for (int i = 0; i < MT; i++)
        #pragma unroll
        for (int j = 0; j < NT; j++)
            #pragma unroll
            for (int k = 0; k < 4; k++) acc[i][j][k] = 0.f;

    const int lrow = lane & 15, lsel = lane >> 4;

    auto compute_k16 = [&](uint32_t stb, int k16) {
        uint32_t ah[MT][4];
        #pragma unroll
        for (int mt = 0; mt < MT; mt++) {
            uint32_t off = (uint32_t)((wm * WTM + mt * 16 + lrow) * AROW +
                                      k16 * 16 + lsel * 8) * 2;
            ldm_x4(ah[mt], stb + off);
        }
        uint32_t bq[NT][2];
        #pragma unroll
        for (int np = 0; np < NT / 2; np++) {
            uint32_t off = (uint32_t)((k16 * 16 + lrow) * WROW + wn * WTN +
                                      np * 16 + lsel * 8) * 2;
            uint32_t r[4];
            ldm_x4t(r, stb + WHO + off);
            bq[2*np][0] = r[0]; bq[2*np][1] = r[1];
            bq[2*np+1][0] = r[2]; bq[2*np+1][1] = r[3];
        }
        #pragma unroll
        for (int mt = 0; mt < MT; mt++)
            #pragma unroll
            for (int nt = 0; nt < NT; nt++) mma_f16(acc[mt][nt], ah[mt], bq[nt]);
    };

    // prologue
    ldgA(0);
    cpW(0, 0);
    stsA(0);

    #pragma unroll 1
    for (int kt = 0; kt < KT; kt++) {
        const int st = kt & 1;
        asm volatile("cp.async.wait_group 0;" ::: "memory");
        __syncthreads();
        const bool more = (kt + 1 < KT);
        if (more) { cpW(kt + 1, st ^ 1); ldgA(kt + 1); }
        const uint32_t stb = sb + st * STAGE;
        compute_k16(stb, 0);
        if (more) stsA(st ^ 1);      // overlapped: writes the other stage
        #pragma unroll
        for (int k16 = 1; k16 < NK16; k16++) compute_k16(stb, k16);
    }
    __syncthreads();   // stage smem dead; reused for output staging + stats

    // ---- epilogue: bias -> SMEM stage (+stats from regs), then coalesced STG ----
    const int r0 = lane >> 2, c0 = (lane & 3) * 2;
    #pragma unroll
    for (int nt = 0; nt < NT; nt++) {
        float2 bv = *(const float2*)(bias + t * NTOT + n0 + wn * WTN + nt * 8 + c0);
        #pragma unroll
        for (int mt = 0; mt < MT; mt++) {
            acc[mt][nt][0] += bv.x; acc[mt][nt][1] += bv.y;
            acc[mt][nt][2] += bv.x; acc[mt][nt][3] += bv.y;
        }
    }
    #pragma unroll
    for (int mt = 0; mt < MT; mt++) {
        #pragma unroll
        for (int nt = 0; nt < NT; nt++) {
            int col = wn * WTN + nt * 8 + c0;
            int row = wm * WTM + mt * 16 + r0;
            OT* p0 = (OT*)(smem + (size_t)row * OROW_B) + col;
            OT* p1 = (OT*)(smem + (size_t)(row + 8) * OROW_B) + col;
            store2(p0, acc[mt][nt][0], acc[mt][nt][1]);
            store2(p1, acc[mt][nt][2], acc[mt][nt][3]);
        }
    }
    if (STATS) {
        float* sbuf = (float*)(smem + SBUF_OFF);   // [4][BN]
        #pragma unroll
        for (int nt = 0; nt < NT; nt++) {
            #pragma unroll
            for (int j = 0; j < 2; j++) {
                float s = 0.f, q = 0.f;
                #pragma unroll
                for (int mt = 0; mt < MT; mt++) {
                    float v0 = acc[mt][nt][j], v1 = acc[mt][nt][2 + j];
                    s += v0 + v1;
                    q = fmaf(v0, v0, q); q = fmaf(v1, v1, q);
                }
                #pragma unroll
                for (int msk = 4; msk <= 16; msk <<= 1) {
                    s += __shfl_xor_sync(0xffffffffu, s, msk);
                    q += __shfl_xor_sync(0xffffffffu, q, msk);
                }
                if (r0 == 0) {
                    int col = wn * WTN + nt * 8 + c0 + j;
                    sbuf[(wm * 2 + 0) * BN + col] = s;
                    sbuf[(wm * 2 + 1) * BN + col] = q;
                }
            }
        }
    }
    __syncthreads();   // staging tile + stats scratch visible
    {
        constexpr int VPR = BN * (int)sizeof(OT) / 16;   // uint4 per row
        #pragma unroll
        for (int i = tid; i < BM * VPR; i += 256) {
            int row = i / VPR, v = i % VPR;
            uint4 val = *(const uint4*)(smem + (size_t)row * OROW_B + v * 16);
            char* dst = (char*)(out + (size_t)t * o_t +
                                (size_t)(m0 + row) * o_rs + n0) + v * 16;
            *(uint4*)dst = val;
        }
    }
    if (STATS) {
        float* sbuf = (float*)(smem + SBUF_OFF);
        for (int cix = tid; cix < BN; cix += 256) {
            float ss = sbuf[0 * BN + cix] + sbuf[2 * BN + cix];
            float qq = sbuf[1 * BN + cix] + sbuf[3 * BN + cix];
            size_t pi = (size_t)blockIdx.y * (TT * NTOT) + (size_t)t * NTOT + n0 + cix;
            g_psum[pi] = ss;
            g_psq [pi] = qq;
        }
    }
}

// ---------------- launch --------------------------------------------------------
extern "C" void kernel_launch(void* const* d_in, const int* in_sizes, int n_in,
                              void* d_out, int out_size) {
    (void)in_sizes; (void)n_in; (void)out_size;
    const float* prices = (const float*)d_in[0];
    const float* bn0_g  = (const float*)d_in[1];
    const float* bn0_b  = (const float*)d_in[2];
    const float* W1     = (const float*)d_in[3];
    const float* b1     = (const float*)d_in[4];
    const float* bn1_g  = (const float*)d_in[5];
    const float* bn1_b  = (const float*)d_in[6];
    const float* W2     = (const float*)d_in[7];
    const float* b2     = (const float*)d_in[8];
    const float* bn2_g  = (const float*)d_in[9];
    const float* bn2_b  = (const float*)d_in[10];
    const float* W3     = (const float*)d_in[11];
    const float* b3     = (const float*)d_in[12];
    float* out = (float*)d_out;

    __half *hp1, *hp2, *w1, *w2, *w3;
    cudaGetSymbolAddress((void**)&hp1, g_h1);
    cudaGetSymbolAddress((void**)&hp2, g_h2);
    cudaGetSymbolAddress((void**)&w1, g_w1);
    cudaGetSymbolAddress((void**)&w2, g_w2);
    cudaGetSymbolAddress((void**)&w3, g_w3);

    const float invB = 1.0f / (float)BB;

    auto g1 = gemm_mma<256, 64, 64,  512, false, true,  float,  __half>;
    auto g2 = gemm_mma<256, 64, 512, 512, true,  true,  __half, __half>;
    auto g3 = gemm_mma<64,  64, 512, 64,  true,  false, __half, float>;
    constexpr int STAGE_256 = 128 * 72 * 2 + 64 * 264 * 2;  // 52224
    constexpr int STAGE_64  = 128 * 72 * 2 + 64 * 72 * 2;   // 27648
    constexpr int SM1 = 67584 + 4096;
    constexpr int SM2 = (2 * STAGE_256 > 67584 + 4096) ? 2 * STAGE_256
                                                       : 67584 + 4096; // 104448
    constexpr int SM3 = 2 * STAGE_64;
    cudaFuncSetAttribute(g1, cudaFuncAttributeMaxDynamicSharedMemorySize, SM1);
    cudaFuncSetAttribute(g2, cudaFuncAttributeMaxDynamicSharedMemorySize, SM2);
    cudaFuncSetAttribute(g3, cudaFuncAttributeMaxDynamicSharedMemorySize, SM3);

    // one-time side stream + events (host resources, not device memory)
    static cudaStream_t s_side = nullptr;
    static cudaEvent_t ev_fork = nullptr, ev_w1 = nullptr, ev_w23 = nullptr;
    if (s_side == nullptr) {
        cudaStreamCreateWithFlags(&s_side, cudaStreamNonBlocking);
        cudaEventCreateWithFlags(&ev_fork, cudaEventDisableTiming);
        cudaEventCreateWithFlags(&ev_w1,   cudaEventDisableTiming);
        cudaEventCreateWithFlags(&ev_w23,  cudaEventDisableTiming);
    }

    // fork: side stream does weight conversion concurrently
    cudaEventRecord(ev_fork, 0);
    cudaStreamWaitEvent(s_side, ev_fork, 0);
    constexpr size_t N1Q = (size_t)TT * PP * HH / 4;
    prep_w1k<<<(int)((N1Q + 255) / 256), 256, 0, s_side>>>(W1);
    cudaEventRecord(ev_w1, s_side);
    constexpr size_t NQ23 = (size_t)TT * (HH * HH + HH * PP) / 4;
    prep_w23<<<(int)((NQ23 + 255) / 256), 256, 0, s_side>>>(W2, W3);
    cudaEventRecord(ev_w23, s_side);

    // main stream: stats -> finalize0 -> (join W1) g1 -> finalize1 -> (join W23) g2 ...
    stats_kernel<<<dim3(TT, SPLITS0), 64>>>(prices, (size_t)PP, TT * PP, PP,
                                            BB / SPLITS0);
    finalize_kernel<<<(TT * PP + 255) / 256, 256>>>(bn0_g, bn0_b, TT * PP, invB,
                                                    SPLITS0);
    cudaStreamWaitEvent(0, ev_w1, 0);
    g1<<<dim3(HH / 256, BB / 128, TT), 256, SM1>>>(
        prices, (size_t)PP, TT * PP, w1, b1, hp1, (size_t)BB * HH, HH);

    finalize_kernel<<<(TT * HH + 255) / 256, 256>>>(bn1_g, bn1_b, TT * HH, invB,
                                                    MBLK);
    cudaStreamWaitEvent(0, ev_w23, 0);
    g2<<<dim3(HH / 256, BB / 128, TT), 256, SM2>>>(
        hp1, (size_t)BB * HH, HH, w2, b2, hp2, (size_t)BB * HH, HH);

    finalize_kernel<<<(TT * HH + 255) / 256, 256>>>(bn2_g, bn2_b, TT * HH, invB,
                                                    MBLK);
    g3<<<dim3(1, BB / 128, TT), 256, SM3>>>(
        hp2, (size_t)BB * HH, HH, w3, b3, out, (size_t)PP, TT * PP);
}